// round 5
// baseline (speedup 1.0000x reference)
#include <cuda_runtime.h>
#include <math.h>

#define Bq   16
#define Sq   256
#define NV   196
#define Dm   768
#define FFd  2048
#define VOC  30522
#define NL   6
#define NHh  8
#define HD   96
#define NTOK (Bq*Sq)        // 4096
#define NMEM (Bq*NV)        // 3136
#define NDEC (Bq*(Sq-1))    // 4080

// -------- scratch (device globals; no allocations allowed) --------
__device__ float g_x   [NTOK*Dm];
__device__ float g_o   [NTOK*Dm];
__device__ float g_attn[NTOK*Dm];
__device__ float g_q   [NTOK*Dm];
__device__ float g_qkv [NTOK*3*Dm];
__device__ float g_kv  [NMEM*2*Dm];
__device__ float g_ff  [NTOK*FFd];
__device__ float g_dec [NDEC*Dm];

// ================== TF32 tensor-core GEMM ==================
// C[M,N] = A[M,K] @ W[N,K]^T (+bias)(+relu), fp32 accumulate.
// 128x128 tile, BK=16, 8 warps of 64x32, double-buffered smem.
// Smem uses a permuted k-layout so fragment loads are single LDS.128:
//   pos(k) = (k&3)*4 + (k>>2)   (within each 16-k row, row stride 16)
//   -> ld.shared.v4 at row*16 + t4*4 yields k = t4, t4+4, t4+8, t4+12.
#define BM 128
#define BN 128
#define BK 16

__device__ __forceinline__ unsigned f2tf(float f) {
    unsigned r;
    asm("cvt.rna.tf32.f32 %0, %1;" : "=r"(r) : "f"(f));
    return r;
}

__device__ __forceinline__ void mma_tf32(
    float& c0, float& c1, float& c2, float& c3,
    unsigned a0, unsigned a1, unsigned a2, unsigned a3,
    unsigned b0, unsigned b1)
{
    asm volatile(
        "mma.sync.aligned.m16n8k8.row.col.f32.tf32.tf32.f32 "
        "{%0,%1,%2,%3}, {%4,%5,%6,%7}, {%8,%9}, {%0,%1,%2,%3};"
        : "+f"(c0), "+f"(c1), "+f"(c2), "+f"(c3)
        : "r"(a0), "r"(a1), "r"(a2), "r"(a3), "r"(b0), "r"(b1));
}

__global__ __launch_bounds__(256, 2) void mma_gemm(
    const float* __restrict__ A, const float* __restrict__ W,
    const float* __restrict__ bias, float* __restrict__ C,
    int M, int N, int K, int relu)
{
    __shared__ float As[2][BM * BK];   // permuted-k layout, row stride 16
    __shared__ float Bs[2][BN * BK];

    int tid  = threadIdx.x;
    int wid  = tid >> 5, lane = tid & 31;
    int g    = lane >> 2;
    int t4   = lane & 3;
    int wm   = (wid >> 2) * 64;
    int wn   = (wid & 3) * 32;
    int m0   = blockIdx.y * BM, n0 = blockIdx.x * BN;

    // global-load mapping: 512 float4 per operand tile, 2 per thread
    int id0 = tid, id1 = tid + 256;
    int r0 = id0 >> 2, c0_ = (id0 & 3) * 4, q0_ = c0_ >> 2;
    int r1 = id1 >> 2, c1_ = (id1 & 3) * 4, q1_ = c1_ >> 2;
    bool av0 = (m0 + r0) < M, av1 = (m0 + r1) < M;
    bool bv0 = (n0 + r0) < N, bv1 = (n0 + r1) < N;
    const float* Ap0 = A + (long)(m0 + r0) * K + c0_;
    const float* Ap1 = A + (long)(m0 + r1) * K + c1_;
    const float* Wp0 = W + (long)(n0 + r0) * K + c0_;
    const float* Wp1 = W + (long)(n0 + r1) * K + c1_;

    float acc[4][4][4];
    #pragma unroll
    for (int i = 0; i < 4; i++)
        #pragma unroll
        for (int j = 0; j < 4; j++)
            #pragma unroll
            for (int k = 0; k < 4; k++) acc[i][j][k] = 0.f;

    const float4 z4 = make_float4(0.f, 0.f, 0.f, 0.f);
    float4 ra0, ra1, rb0, rb1;

    // store one float4 (4 consecutive logical k) into permuted layout
    #define STORE_PERM(dst, row, qq, v)                                   \
        { float* _p = (dst) + (row) * BK + (qq);                          \
          _p[0]  = __uint_as_float(f2tf((v).x));                          \
          _p[4]  = __uint_as_float(f2tf((v).y));                          \
          _p[8]  = __uint_as_float(f2tf((v).z));                          \
          _p[12] = __uint_as_float(f2tf((v).w)); }

    // prologue: tile 0
    ra0 = av0 ? *(const float4*)(Ap0) : z4;
    ra1 = av1 ? *(const float4*)(Ap1) : z4;
    rb0 = bv0 ? *(const float4*)(Wp0) : z4;
    rb1 = bv1 ? *(const float4*)(Wp1) : z4;
    STORE_PERM(As[0], r0, q0_, ra0);
    STORE_PERM(As[0], r1, q1_, ra1);
    STORE_PERM(Bs[0], r0, q0_, rb0);
    STORE_PERM(Bs[0], r1, q1_, rb1);
    __syncthreads();

    int nk = K / BK;
    int buf = 0;
    for (int t = 0; t < nk; t++) {
        if (t + 1 < nk) {
            int ko = (t + 1) * BK;
            ra0 = av0 ? *(const float4*)(Ap0 + ko) : z4;
            ra1 = av1 ? *(const float4*)(Ap1 + ko) : z4;
            rb0 = bv0 ? *(const float4*)(Wp0 + ko) : z4;
            rb1 = bv1 ? *(const float4*)(Wp1 + ko) : z4;
        }
        const float* as = As[buf];
        const float* bs = Bs[buf];

        float4 alo[4], ahi[4], bv[4];
        #pragma unroll
        for (int mt = 0; mt < 4; mt++) {
            int row = wm + mt * 16 + g;
            alo[mt] = *(const float4*)&as[row * BK + t4 * 4];
            ahi[mt] = *(const float4*)&as[(row + 8) * BK + t4 * 4];
        }
        #pragma unroll
        for (int nt = 0; nt < 4; nt++) {
            int row = wn + nt * 8 + g;
            bv[nt] = *(const float4*)&bs[row * BK + t4 * 4];
        }
        #pragma unroll
        for (int mt = 0; mt < 4; mt++)
            #pragma unroll
            for (int nt = 0; nt < 4; nt++) {
                // ks = 0..7 chunk
                mma_tf32(acc[mt][nt][0], acc[mt][nt][1], acc[mt][nt][2], acc[mt][nt][3],
                         __float_as_uint(alo[mt].x), __float_as_uint(ahi[mt].x),
                         __float_as_uint(alo[mt].y), __float_as_uint(ahi[mt].y),
                         __float_as_uint(bv[nt].x),  __float_as_uint(bv[nt].y));
                // ks = 8..15 chunk
                mma_tf32(acc[mt][nt][0], acc[mt][nt][1], acc[mt][nt][2], acc[mt][nt][3],
                         __float_as_uint(alo[mt].z), __float_as_uint(ahi[mt].z),
                         __float_as_uint(alo[mt].w), __float_as_uint(ahi[mt].w),
                         __float_as_uint(bv[nt].z),  __float_as_uint(bv[nt].w));
            }

        if (t + 1 < nk) {
            __syncthreads();
            float* nas = As[buf ^ 1]; float* nbs = Bs[buf ^ 1];
            STORE_PERM(nas, r0, q0_, ra0);
            STORE_PERM(nas, r1, q1_, ra1);
            STORE_PERM(nbs, r0, q0_, rb0);
            STORE_PERM(nbs, r1, q1_, rb1);
            __syncthreads();
            buf ^= 1;
        }
    }
    #undef STORE_PERM

    // epilogue
    #pragma unroll
    for (int mt = 0; mt < 4; mt++) {
        int row = m0 + wm + mt * 16 + g;
        #pragma unroll
        for (int nt = 0; nt < 4; nt++) {
            int col = n0 + wn + nt * 8 + t4 * 2;
            float v0 = acc[mt][nt][0], v1 = acc[mt][nt][1];
            float v2 = acc[mt][nt][2], v3 = acc[mt][nt][3];
            if (bias) {
                float b0 = (col < N) ? bias[col] : 0.f;
                float b1 = (col + 1 < N) ? bias[col + 1] : 0.f;
                v0 += b0; v1 += b1; v2 += b0; v3 += b1;
            }
            if (relu) {
                v0 = fmaxf(v0, 0.f); v1 = fmaxf(v1, 0.f);
                v2 = fmaxf(v2, 0.f); v3 = fmaxf(v3, 0.f);
            }
            if (row < M) {
                if (col + 1 < N) *(float2*)&C[(long)row * N + col] = make_float2(v0, v1);
                else if (col < N) C[(long)row * N + col] = v0;
            }
            if (row + 8 < M) {
                if (col + 1 < N) *(float2*)&C[(long)(row + 8) * N + col] = make_float2(v2, v3);
                else if (col < N) C[(long)(row + 8) * N + col] = v2;
            }
        }
    }
}

// ================== tiled smem attention ==================
#define TQ 16
#define KCH 32

__global__ __launch_bounds__(128) void attn_tile(
    const float* __restrict__ Q, int qs,
    const float* __restrict__ Kt, int ks,
    const float* __restrict__ Vt, int vs,
    float* __restrict__ O, int os,
    int Lk, int causal)
{
    __shared__ float Qs[TQ][97];
    __shared__ float Ks[KCH][97];
    __shared__ float Vs[KCH][HD];
    __shared__ float Sc[TQ][Sq];
    __shared__ float invr[TQ];

    int tid  = threadIdx.x;
    int warp = tid >> 5, lane = tid & 31;
    int q0   = blockIdx.x * TQ;
    int h    = blockIdx.y, b = blockIdx.z;

    const float* Qb = Q  + ((long)b * Sq + q0) * qs + h * HD;
    const float* Kb = Kt + (long)b * Lk * ks + h * HD;
    const float* Vb = Vt + (long)b * Lk * vs + h * HD;

    for (int i = tid; i < TQ * HD; i += 128) {
        int r = i / HD, c = i % HD;
        Qs[r][c] = Qb[(long)r * qs + c];
    }

    const float scale = rsqrtf((float)HD);
    int nch = (Lk + KCH - 1) / KCH;

    for (int kc = 0; kc < nch; kc++) {
        int k0 = kc * KCH;
        __syncthreads();
        for (int i = tid; i < KCH * HD; i += 128) {
            int r = i / HD, c = i % HD;
            Ks[r][c] = (k0 + r < Lk) ? Kb[(long)(k0 + r) * ks + c] : 0.f;
        }
        __syncthreads();
        int j = k0 + lane;
        float s0 = 0.f, s1 = 0.f, s2 = 0.f, s3 = 0.f;
        #pragma unroll 8
        for (int t = 0; t < HD; t++) {
            float kv = Ks[lane][t];
            s0 += Qs[warp*4+0][t] * kv;
            s1 += Qs[warp*4+1][t] * kv;
            s2 += Qs[warp*4+2][t] * kv;
            s3 += Qs[warp*4+3][t] * kv;
        }
        #pragma unroll
        for (int qi = 0; qi < 4; qi++) {
            int q = warp * 4 + qi;
            float s = (qi == 0) ? s0 : (qi == 1) ? s1 : (qi == 2) ? s2 : s3;
            s *= scale;
            if (j >= Lk || (causal && j > q0 + q)) s = -1e30f;
            Sc[q][j] = s;
        }
    }
    __syncthreads();

    int nk32 = nch * KCH;
    #pragma unroll
    for (int qi = 0; qi < 4; qi++) {
        int q = warp * 4 + qi;
        float mx = -1e30f;
        for (int j = lane; j < nk32; j += 32) mx = fmaxf(mx, Sc[q][j]);
        #pragma unroll
        for (int o = 16; o; o >>= 1) mx = fmaxf(mx, __shfl_xor_sync(~0u, mx, o));
        float sum = 0.f;
        for (int j = lane; j < nk32; j += 32) {
            float e = __expf(Sc[q][j] - mx);
            Sc[q][j] = e;
            sum += e;
        }
        #pragma unroll
        for (int o = 16; o; o >>= 1) sum += __shfl_xor_sync(~0u, sum, o);
        if (lane == 0) invr[q] = 1.f / sum;
    }

    int qa = tid >> 3;
    int dbase = (tid & 7) * 12;
    float acc[12];
    #pragma unroll
    for (int i = 0; i < 12; i++) acc[i] = 0.f;

    for (int kc = 0; kc < nch; kc++) {
        int k0 = kc * KCH;
        __syncthreads();
        for (int i = tid; i < KCH * HD; i += 128) {
            int r = i / HD, c = i % HD;
            Vs[r][c] = (k0 + r < Lk) ? Vb[(long)(k0 + r) * vs + c] : 0.f;
        }
        __syncthreads();
        #pragma unroll
        for (int j = 0; j < KCH; j++) {
            float p = Sc[qa][k0 + j];
            float4 v0 = *(const float4*)&Vs[j][dbase];
            float4 v1 = *(const float4*)&Vs[j][dbase + 4];
            float4 v2 = *(const float4*)&Vs[j][dbase + 8];
            acc[0] += p * v0.x; acc[1]  += p * v0.y; acc[2]  += p * v0.z; acc[3]  += p * v0.w;
            acc[4] += p * v1.x; acc[5]  += p * v1.y; acc[6]  += p * v1.z; acc[7]  += p * v1.w;
            acc[8] += p * v2.x; acc[9]  += p * v2.y; acc[10] += p * v2.z; acc[11] += p * v2.w;
        }
    }
    float inv = invr[qa];
    float* op = O + ((long)b * Sq + q0 + qa) * os + h * HD + dbase;
    *(float4*)&op[0] = make_float4(acc[0]*inv, acc[1]*inv, acc[2]*inv, acc[3]*inv);
    *(float4*)&op[4] = make_float4(acc[4]*inv, acc[5]*inv, acc[6]*inv, acc[7]*inv);
    *(float4*)&op[8] = make_float4(acc[8]*inv, acc[9]*inv, acc[10]*inv, acc[11]*inv);
}

// -------- residual add + layernorm (in-place on X) --------
__global__ __launch_bounds__(256) void add_ln_kernel(
    float* __restrict__ X, const float* __restrict__ Y,
    const float* __restrict__ w, const float* __restrict__ b)
{
    long t = blockIdx.x;
    int tid = threadIdx.x;
    __shared__ float red[256];
    float vals[3];
    float s = 0.f;
    #pragma unroll
    for (int i = 0; i < 3; i++) {
        int d = tid + i * 256;
        float v = X[t * Dm + d] + Y[t * Dm + d];
        vals[i] = v;
        s += v;
    }
    red[tid] = s; __syncthreads();
    for (int st = 128; st > 0; st >>= 1) {
        if (tid < st) red[tid] += red[tid + st];
        __syncthreads();
    }
    float mean = red[0] * (1.f / Dm);
    __syncthreads();
    float s2 = 0.f;
    #pragma unroll
    for (int i = 0; i < 3; i++) { float dv = vals[i] - mean; s2 += dv * dv; }
    red[tid] = s2; __syncthreads();
    for (int st = 128; st > 0; st >>= 1) {
        if (tid < st) red[tid] += red[tid + st];
        __syncthreads();
    }
    float rstd = rsqrtf(red[0] * (1.f / Dm) + 1e-5f);
    #pragma unroll
    for (int i = 0; i < 3; i++) {
        int d = tid + i * 256;
        X[t * Dm + d] = (vals[i] - mean) * rstd * w[d] + b[d];
    }
}

// -------- x = target_embed + sinusoid PE --------
__global__ void pe_kernel(const float* __restrict__ te, float* __restrict__ x)
{
    int idx = blockIdx.x * 256 + threadIdx.x;
    if (idx >= NTOK * Dm) return;
    int d = idx % Dm;
    int tok = idx / Dm;
    int s = tok % Sq;
    int j = d >> 1;
    float div = expf(-(float)(2 * j) * (logf(10000.f) / (float)Dm));
    float ang = (float)s * div;
    float p = (d & 1) ? cosf(ang) : sinf(ang);
    x[idx] = te[idx] + p;
}

// -------- gather dec = x[:, :S-1, :] --------
__global__ void dec_gather(const float* __restrict__ x, float* __restrict__ dec)
{
    int idx = blockIdx.x * 256 + threadIdx.x;
    if (idx >= NDEC * Dm) return;
    int d = idx % Dm;
    int r = idx / Dm;
    int b = r / (Sq - 1);
    int s = r % (Sq - 1);
    dec[idx] = x[((long)(b * Sq + s)) * Dm + d];
}

// -------- F_t = softmax(dec, axis=-1) --------
__global__ __launch_bounds__(256) void ft_softmax(
    const float* __restrict__ dec, float* __restrict__ out)
{
    long r = blockIdx.x;
    int tid = threadIdx.x;
    __shared__ float red[256];
    float v[3];
    float mx = -1e30f;
    #pragma unroll
    for (int i = 0; i < 3; i++) {
        v[i] = dec[r * Dm + tid + i * 256];
        mx = fmaxf(mx, v[i]);
    }
    red[tid] = mx; __syncthreads();
    for (int st = 128; st > 0; st >>= 1) {
        if (tid < st) red[tid] = fmaxf(red[tid], red[tid + st]);
        __syncthreads();
    }
    float m = red[0]; __syncthreads();
    float s = 0.f;
    #pragma unroll
    for (int i = 0; i < 3; i++) { v[i] = __expf(v[i] - m); s += v[i]; }
    red[tid] = s; __syncthreads();
    for (int st = 128; st > 0; st >>= 1) {
        if (tid < st) red[tid] += red[tid + st];
        __syncthreads();
    }
    float inv = 1.f / red[0];
    #pragma unroll
    for (int i = 0; i < 3; i++)
        out[r * Dm + tid + i * 256] = v[i] * inv;
}

static inline dim3 gemm_grid(int M, int N) {
    return dim3((N + 127) / 128, (M + 127) / 128);
}

extern "C" void kernel_launch(void* const* d_in, const int* in_sizes, int n_in,
                              void* d_out, int out_size)
{
    const float* fv          = (const float*)d_in[0];
    const float* te          = (const float*)d_in[1];
    const float* self_in_w   = (const float*)d_in[2];
    const float* self_in_b   = (const float*)d_in[3];
    const float* self_out_w  = (const float*)d_in[4];
    const float* self_out_b  = (const float*)d_in[5];
    const float* cross_in_w  = (const float*)d_in[6];
    const float* cross_in_b  = (const float*)d_in[7];
    const float* cross_out_w = (const float*)d_in[8];
    const float* cross_out_b = (const float*)d_in[9];
    const float* lin1_w      = (const float*)d_in[10];
    const float* lin1_b      = (const float*)d_in[11];
    const float* lin2_w      = (const float*)d_in[12];
    const float* lin2_b      = (const float*)d_in[13];
    const float* ln_w        = (const float*)d_in[14];
    const float* ln_b        = (const float*)d_in[15];
    const float* fc_out_w    = (const float*)d_in[16];

    float* out    = (float*)d_out;
    float* logits = out;
    float* ft     = out + (long)NDEC * VOC;

    float *px, *po, *pattn, *pq, *pqkv, *pkv, *pff, *pdec;
    cudaGetSymbolAddress((void**)&px,    g_x);
    cudaGetSymbolAddress((void**)&po,    g_o);
    cudaGetSymbolAddress((void**)&pattn, g_attn);
    cudaGetSymbolAddress((void**)&pq,    g_q);
    cudaGetSymbolAddress((void**)&pqkv,  g_qkv);
    cudaGetSymbolAddress((void**)&pkv,   g_kv);
    cudaGetSymbolAddress((void**)&pff,   g_ff);
    cudaGetSymbolAddress((void**)&pdec,  g_dec);

    pe_kernel<<<(NTOK * Dm + 255) / 256, 256>>>(te, px);

    dim3 agrid(Sq / TQ, NHh, Bq);

    for (int l = 0; l < NL; l++) {
        const float* siw = self_in_w  + (long)l * 3 * Dm * Dm;
        const float* sib = self_in_b  + (long)l * 3 * Dm;
        const float* sow = self_out_w + (long)l * Dm * Dm;
        const float* sob = self_out_b + (long)l * Dm;
        const float* ciw = cross_in_w  + (long)l * 3 * Dm * Dm;
        const float* cib = cross_in_b  + (long)l * 3 * Dm;
        const float* cow = cross_out_w + (long)l * Dm * Dm;
        const float* cob = cross_out_b + (long)l * Dm;
        const float* l1w = lin1_w + (long)l * FFd * Dm;
        const float* l1b = lin1_b + (long)l * FFd;
        const float* l2w = lin2_w + (long)l * Dm * FFd;
        const float* l2b = lin2_b + (long)l * Dm;
        const float* lw  = ln_w + (long)l * 3 * Dm;
        const float* lb  = ln_b + (long)l * 3 * Dm;

        // ---- self attention ----
        mma_gemm<<<gemm_grid(NTOK, 3 * Dm), 256>>>(px, siw, sib, pqkv,
                                                   NTOK, 3 * Dm, Dm, 0);
        attn_tile<<<agrid, 128>>>(pqkv, 3 * Dm,
                                  pqkv + Dm, 3 * Dm,
                                  pqkv + 2 * Dm, 3 * Dm,
                                  pattn, Dm, Sq, 1);
        mma_gemm<<<gemm_grid(NTOK, Dm), 256>>>(pattn, sow, sob, po,
                                               NTOK, Dm, Dm, 0);
        add_ln_kernel<<<NTOK, 256>>>(px, po, lw, lb);

        // ---- cross attention ----
        mma_gemm<<<gemm_grid(NTOK, Dm), 256>>>(px, ciw, cib, pq,
                                               NTOK, Dm, Dm, 0);
        mma_gemm<<<gemm_grid(NMEM, 2 * Dm), 256>>>(fv, ciw + (long)Dm * Dm,
                                                   cib + Dm, pkv,
                                                   NMEM, 2 * Dm, Dm, 0);
        attn_tile<<<agrid, 128>>>(pq, Dm,
                                  pkv, 2 * Dm,
                                  pkv + Dm, 2 * Dm,
                                  pattn, Dm, NV, 0);
        mma_gemm<<<gemm_grid(NTOK, Dm), 256>>>(pattn, cow, cob, po,
                                               NTOK, Dm, Dm, 0);
        add_ln_kernel<<<NTOK, 256>>>(px, po, lw + Dm, lb + Dm);

        // ---- FFN ----
        mma_gemm<<<gemm_grid(NTOK, FFd), 256>>>(px, l1w, l1b, pff,
                                                NTOK, FFd, Dm, 1);
        mma_gemm<<<gemm_grid(NTOK, Dm), 256>>>(pff, l2w, l2b, po,
                                               NTOK, Dm, FFd, 0);
        add_ln_kernel<<<NTOK, 256>>>(px, po, lw + 2 * Dm, lb + 2 * Dm);
    }

    dec_gather<<<(NDEC * Dm + 255) / 256, 256>>>(px, pdec);
    mma_gemm<<<gemm_grid(NDEC, VOC), 256>>>(pdec, fc_out_w, nullptr, logits,
                                            NDEC, VOC, Dm, 0);
    ft_softmax<<<NDEC, 256>>>(pdec, ft);
}

// round 6
// speedup vs baseline: 1.0507x; 1.0507x over previous
#include <cuda_runtime.h>
#include <math.h>

#define Bq   16
#define Sq   256
#define NV   196
#define Dm   768
#define FFd  2048
#define VOC  30522
#define NL   6
#define NHh  8
#define HD   96
#define NTOK (Bq*Sq)        // 4096
#define NMEM (Bq*NV)        // 3136
#define NDEC (Bq*(Sq-1))    // 4080

// -------- scratch (device globals; no allocations allowed) --------
__device__ float g_x   [NTOK*Dm];
__device__ float g_o   [NTOK*Dm];
__device__ float g_attn[NTOK*Dm];
__device__ float g_q   [NTOK*Dm];
__device__ float g_qkv [NTOK*3*Dm];
__device__ float g_kv  [NMEM*2*Dm];
__device__ float g_ff  [NTOK*FFd];
__device__ float g_dec [NDEC*Dm];

// ================== TF32 tensor-core GEMM ==================
// C[M,N] = A[M,K] @ W[N,K]^T (+bias)(+relu), fp32 accumulate.
// 128x64 block tile, BK=16, 4 warps each 64x32, double-buffered smem.
// Small CTA -> dense multi-CTA residency (grid-limited occupancy fix).
#define BM 128
#define BN 64
#define BK 16
#define PAD 20   // conflict-free for scalar fragment reads & stores

__device__ __forceinline__ unsigned f2tf(float f) {
    unsigned r;
    asm("cvt.rna.tf32.f32 %0, %1;" : "=r"(r) : "f"(f));
    return r;
}

__device__ __forceinline__ void mma_tf32(
    float& c0, float& c1, float& c2, float& c3,
    unsigned a0, unsigned a1, unsigned a2, unsigned a3,
    unsigned b0, unsigned b1)
{
    asm volatile(
        "mma.sync.aligned.m16n8k8.row.col.f32.tf32.tf32.f32 "
        "{%0,%1,%2,%3}, {%4,%5,%6,%7}, {%8,%9}, {%0,%1,%2,%3};"
        : "+f"(c0), "+f"(c1), "+f"(c2), "+f"(c3)
        : "r"(a0), "r"(a1), "r"(a2), "r"(a3), "r"(b0), "r"(b1));
}

__global__ __launch_bounds__(128, 4) void mma_gemm(
    const float* __restrict__ A, const float* __restrict__ W,
    const float* __restrict__ bias, float* __restrict__ C,
    int M, int N, int K, int relu)
{
    __shared__ float As[2][BM * PAD];
    __shared__ float Bs[2][BN * PAD];

    int tid  = threadIdx.x;
    int wid  = tid >> 5, lane = tid & 31;
    int g    = lane >> 2;          // 0..7
    int t4   = lane & 3;           // 0..3
    int wm   = (wid >> 1) * 64;    // 0 / 64
    int wn   = (wid & 1) * 32;     // 0 / 32
    int m0   = blockIdx.y * BM, n0 = blockIdx.x * BN;

    // global-load mapping:
    // A tile: 512 float4 -> 4 per thread; B tile: 256 float4 -> 2 per thread
    int ar[4], ac[4]; bool avv[4];
    const float* Apt[4];
    #pragma unroll
    for (int i = 0; i < 4; i++) {
        int idx = tid + i * 128;
        ar[i] = idx >> 2; ac[i] = (idx & 3) * 4;
        avv[i] = (m0 + ar[i]) < M;
        Apt[i] = A + (long)(m0 + ar[i]) * K + ac[i];
    }
    int br[2], bc[2]; bool bvv[2];
    const float* Wpt[2];
    #pragma unroll
    for (int i = 0; i < 2; i++) {
        int idx = tid + i * 128;
        br[i] = idx >> 2; bc[i] = (idx & 3) * 4;
        bvv[i] = (n0 + br[i]) < N;
        Wpt[i] = W + (long)(n0 + br[i]) * K + bc[i];
    }

    float acc[4][4][4];
    #pragma unroll
    for (int i = 0; i < 4; i++)
        #pragma unroll
        for (int j = 0; j < 4; j++)
            #pragma unroll
            for (int k = 0; k < 4; k++) acc[i][j][k] = 0.f;

    const float4 z4 = make_float4(0.f, 0.f, 0.f, 0.f);
    float4 rva[4], rvb[2];

    #define STORE_T(dst, row, col, v)                              \
        { float* _p = (dst) + (row) * PAD + (col);                 \
          _p[0] = __uint_as_float(f2tf((v).x));                    \
          _p[1] = __uint_as_float(f2tf((v).y));                    \
          _p[2] = __uint_as_float(f2tf((v).z));                    \
          _p[3] = __uint_as_float(f2tf((v).w)); }

    // prologue: tile 0
    #pragma unroll
    for (int i = 0; i < 4; i++) rva[i] = avv[i] ? *(const float4*)(Apt[i]) : z4;
    #pragma unroll
    for (int i = 0; i < 2; i++) rvb[i] = bvv[i] ? *(const float4*)(Wpt[i]) : z4;
    #pragma unroll
    for (int i = 0; i < 4; i++) STORE_T(As[0], ar[i], ac[i], rva[i]);
    #pragma unroll
    for (int i = 0; i < 2; i++) STORE_T(Bs[0], br[i], bc[i], rvb[i]);
    __syncthreads();

    int nk = K / BK;
    int buf = 0;
    for (int t = 0; t < nk; t++) {
        if (t + 1 < nk) {
            int ko = (t + 1) * BK;
            #pragma unroll
            for (int i = 0; i < 4; i++) rva[i] = avv[i] ? *(const float4*)(Apt[i] + ko) : z4;
            #pragma unroll
            for (int i = 0; i < 2; i++) rvb[i] = bvv[i] ? *(const float4*)(Wpt[i] + ko) : z4;
        }
        const float* as = As[buf];
        const float* bs = Bs[buf];
        #pragma unroll
        for (int ks = 0; ks < BK; ks += 8) {
            unsigned af[4][4], bf[4][2];
            #pragma unroll
            for (int mt = 0; mt < 4; mt++) {
                int row = wm + mt * 16 + g;
                af[mt][0] = __float_as_uint(as[row*PAD + ks + t4]);
                af[mt][1] = __float_as_uint(as[(row+8)*PAD + ks + t4]);
                af[mt][2] = __float_as_uint(as[row*PAD + ks + t4 + 4]);
                af[mt][3] = __float_as_uint(as[(row+8)*PAD + ks + t4 + 4]);
            }
            #pragma unroll
            for (int nt = 0; nt < 4; nt++) {
                int row = wn + nt * 8 + g;
                bf[nt][0] = __float_as_uint(bs[row*PAD + ks + t4]);
                bf[nt][1] = __float_as_uint(bs[row*PAD + ks + t4 + 4]);
            }
            #pragma unroll
            for (int mt = 0; mt < 4; mt++)
                #pragma unroll
                for (int nt = 0; nt < 4; nt++)
                    mma_tf32(acc[mt][nt][0], acc[mt][nt][1], acc[mt][nt][2], acc[mt][nt][3],
                             af[mt][0], af[mt][1], af[mt][2], af[mt][3],
                             bf[nt][0], bf[nt][1]);
        }
        if (t + 1 < nk) {
            __syncthreads();
            float* nas = As[buf ^ 1]; float* nbs = Bs[buf ^ 1];
            #pragma unroll
            for (int i = 0; i < 4; i++) STORE_T(nas, ar[i], ac[i], rva[i]);
            #pragma unroll
            for (int i = 0; i < 2; i++) STORE_T(nbs, br[i], bc[i], rvb[i]);
            __syncthreads();
            buf ^= 1;
        }
    }
    #undef STORE_T

    // epilogue
    #pragma unroll
    for (int mt = 0; mt < 4; mt++) {
        int row = m0 + wm + mt * 16 + g;
        #pragma unroll
        for (int nt = 0; nt < 4; nt++) {
            int col = n0 + wn + nt * 8 + t4 * 2;
            float v0 = acc[mt][nt][0], v1 = acc[mt][nt][1];
            float v2 = acc[mt][nt][2], v3 = acc[mt][nt][3];
            if (bias) {
                float b0 = (col < N) ? bias[col] : 0.f;
                float b1 = (col + 1 < N) ? bias[col + 1] : 0.f;
                v0 += b0; v1 += b1; v2 += b0; v3 += b1;
            }
            if (relu) {
                v0 = fmaxf(v0, 0.f); v1 = fmaxf(v1, 0.f);
                v2 = fmaxf(v2, 0.f); v3 = fmaxf(v3, 0.f);
            }
            if (row < M) {
                if (col + 1 < N) *(float2*)&C[(long)row * N + col] = make_float2(v0, v1);
                else if (col < N) C[(long)row * N + col] = v0;
            }
            if (row + 8 < M) {
                if (col + 1 < N) *(float2*)&C[(long)(row + 8) * N + col] = make_float2(v2, v3);
                else if (col < N) C[(long)(row + 8) * N + col] = v2;
            }
        }
    }
}

// ================== tiled smem attention ==================
#define TQ 16
#define KCH 32

__global__ __launch_bounds__(128) void attn_tile(
    const float* __restrict__ Q, int qs,
    const float* __restrict__ Kt, int ks,
    const float* __restrict__ Vt, int vs,
    float* __restrict__ O, int os,
    int Lk, int causal)
{
    __shared__ float Qs[TQ][97];
    __shared__ float Ks[KCH][97];
    __shared__ float Vs[KCH][HD];
    __shared__ float Sc[TQ][Sq];
    __shared__ float invr[TQ];

    int tid  = threadIdx.x;
    int warp = tid >> 5, lane = tid & 31;
    int q0   = blockIdx.x * TQ;
    int h    = blockIdx.y, b = blockIdx.z;

    const float* Qb = Q  + ((long)b * Sq + q0) * qs + h * HD;
    const float* Kb = Kt + (long)b * Lk * ks + h * HD;
    const float* Vb = Vt + (long)b * Lk * vs + h * HD;

    for (int i = tid; i < TQ * HD; i += 128) {
        int r = i / HD, c = i % HD;
        Qs[r][c] = Qb[(long)r * qs + c];
    }

    const float scale = rsqrtf((float)HD);
    int nch = (Lk + KCH - 1) / KCH;

    for (int kc = 0; kc < nch; kc++) {
        int k0 = kc * KCH;
        __syncthreads();
        for (int i = tid; i < KCH * HD; i += 128) {
            int r = i / HD, c = i % HD;
            Ks[r][c] = (k0 + r < Lk) ? Kb[(long)(k0 + r) * ks + c] : 0.f;
        }
        __syncthreads();
        int j = k0 + lane;
        float s0 = 0.f, s1 = 0.f, s2 = 0.f, s3 = 0.f;
        #pragma unroll 8
        for (int t = 0; t < HD; t++) {
            float kv = Ks[lane][t];
            s0 += Qs[warp*4+0][t] * kv;
            s1 += Qs[warp*4+1][t] * kv;
            s2 += Qs[warp*4+2][t] * kv;
            s3 += Qs[warp*4+3][t] * kv;
        }
        #pragma unroll
        for (int qi = 0; qi < 4; qi++) {
            int q = warp * 4 + qi;
            float s = (qi == 0) ? s0 : (qi == 1) ? s1 : (qi == 2) ? s2 : s3;
            s *= scale;
            if (j >= Lk || (causal && j > q0 + q)) s = -1e30f;
            Sc[q][j] = s;
        }
    }
    __syncthreads();

    int nk32 = nch * KCH;
    #pragma unroll
    for (int qi = 0; qi < 4; qi++) {
        int q = warp * 4 + qi;
        float mx = -1e30f;
        for (int j = lane; j < nk32; j += 32) mx = fmaxf(mx, Sc[q][j]);
        #pragma unroll
        for (int o = 16; o; o >>= 1) mx = fmaxf(mx, __shfl_xor_sync(~0u, mx, o));
        float sum = 0.f;
        for (int j = lane; j < nk32; j += 32) {
            float e = __expf(Sc[q][j] - mx);
            Sc[q][j] = e;
            sum += e;
        }
        #pragma unroll
        for (int o = 16; o; o >>= 1) sum += __shfl_xor_sync(~0u, sum, o);
        if (lane == 0) invr[q] = 1.f / sum;
    }

    int qa = tid >> 3;
    int dbase = (tid & 7) * 12;
    float acc[12];
    #pragma unroll
    for (int i = 0; i < 12; i++) acc[i] = 0.f;

    for (int kc = 0; kc < nch; kc++) {
        int k0 = kc * KCH;
        __syncthreads();
        for (int i = tid; i < KCH * HD; i += 128) {
            int r = i / HD, c = i % HD;
            Vs[r][c] = (k0 + r < Lk) ? Vb[(long)(k0 + r) * vs + c] : 0.f;
        }
        __syncthreads();
        #pragma unroll
        for (int j = 0; j < KCH; j++) {
            float p = Sc[qa][k0 + j];
            float4 v0 = *(const float4*)&Vs[j][dbase];
            float4 v1 = *(const float4*)&Vs[j][dbase + 4];
            float4 v2 = *(const float4*)&Vs[j][dbase + 8];
            acc[0] += p * v0.x; acc[1]  += p * v0.y; acc[2]  += p * v0.z; acc[3]  += p * v0.w;
            acc[4] += p * v1.x; acc[5]  += p * v1.y; acc[6]  += p * v1.z; acc[7]  += p * v1.w;
            acc[8] += p * v2.x; acc[9]  += p * v2.y; acc[10] += p * v2.z; acc[11] += p * v2.w;
        }
    }
    float inv = invr[qa];
    float* op = O + ((long)b * Sq + q0 + qa) * os + h * HD + dbase;
    *(float4*)&op[0] = make_float4(acc[0]*inv, acc[1]*inv, acc[2]*inv, acc[3]*inv);
    *(float4*)&op[4] = make_float4(acc[4]*inv, acc[5]*inv, acc[6]*inv, acc[7]*inv);
    *(float4*)&op[8] = make_float4(acc[8]*inv, acc[9]*inv, acc[10]*inv, acc[11]*inv);
}

// -------- residual add + layernorm (in-place on X) --------
__global__ __launch_bounds__(256) void add_ln_kernel(
    float* __restrict__ X, const float* __restrict__ Y,
    const float* __restrict__ w, const float* __restrict__ b)
{
    long t = blockIdx.x;
    int tid = threadIdx.x;
    __shared__ float red[256];
    float vals[3];
    float s = 0.f;
    #pragma unroll
    for (int i = 0; i < 3; i++) {
        int d = tid + i * 256;
        float v = X[t * Dm + d] + Y[t * Dm + d];
        vals[i] = v;
        s += v;
    }
    red[tid] = s; __syncthreads();
    for (int st = 128; st > 0; st >>= 1) {
        if (tid < st) red[tid] += red[tid + st];
        __syncthreads();
    }
    float mean = red[0] * (1.f / Dm);
    __syncthreads();
    float s2 = 0.f;
    #pragma unroll
    for (int i = 0; i < 3; i++) { float dv = vals[i] - mean; s2 += dv * dv; }
    red[tid] = s2; __syncthreads();
    for (int st = 128; st > 0; st >>= 1) {
        if (tid < st) red[tid] += red[tid + st];
        __syncthreads();
    }
    float rstd = rsqrtf(red[0] * (1.f / Dm) + 1e-5f);
    #pragma unroll
    for (int i = 0; i < 3; i++) {
        int d = tid + i * 256;
        X[t * Dm + d] = (vals[i] - mean) * rstd * w[d] + b[d];
    }
}

// -------- x = target_embed + sinusoid PE --------
__global__ void pe_kernel(const float* __restrict__ te, float* __restrict__ x)
{
    int idx = blockIdx.x * 256 + threadIdx.x;
    if (idx >= NTOK * Dm) return;
    int d = idx % Dm;
    int tok = idx / Dm;
    int s = tok % Sq;
    int j = d >> 1;
    float div = expf(-(float)(2 * j) * (logf(10000.f) / (float)Dm));
    float ang = (float)s * div;
    float p = (d & 1) ? cosf(ang) : sinf(ang);
    x[idx] = te[idx] + p;
}

// -------- gather dec = x[:, :S-1, :] --------
__global__ void dec_gather(const float* __restrict__ x, float* __restrict__ dec)
{
    int idx = blockIdx.x * 256 + threadIdx.x;
    if (idx >= NDEC * Dm) return;
    int d = idx % Dm;
    int r = idx / Dm;
    int b = r / (Sq - 1);
    int s = r % (Sq - 1);
    dec[idx] = x[((long)(b * Sq + s)) * Dm + d];
}

// -------- F_t = softmax(dec, axis=-1) --------
__global__ __launch_bounds__(256) void ft_softmax(
    const float* __restrict__ dec, float* __restrict__ out)
{
    long r = blockIdx.x;
    int tid = threadIdx.x;
    __shared__ float red[256];
    float v[3];
    float mx = -1e30f;
    #pragma unroll
    for (int i = 0; i < 3; i++) {
        v[i] = dec[r * Dm + tid + i * 256];
        mx = fmaxf(mx, v[i]);
    }
    red[tid] = mx; __syncthreads();
    for (int st = 128; st > 0; st >>= 1) {
        if (tid < st) red[tid] = fmaxf(red[tid], red[tid + st]);
        __syncthreads();
    }
    float m = red[0]; __syncthreads();
    float s = 0.f;
    #pragma unroll
    for (int i = 0; i < 3; i++) { v[i] = __expf(v[i] - m); s += v[i]; }
    red[tid] = s; __syncthreads();
    for (int st = 128; st > 0; st >>= 1) {
        if (tid < st) red[tid] += red[tid + st];
        __syncthreads();
    }
    float inv = 1.f / red[0];
    #pragma unroll
    for (int i = 0; i < 3; i++)
        out[r * Dm + tid + i * 256] = v[i] * inv;
}

static inline dim3 gemm_grid(int M, int N) {
    return dim3((N + BN - 1) / BN, (M + BM - 1) / BM);
}

extern "C" void kernel_launch(void* const* d_in, const int* in_sizes, int n_in,
                              void* d_out, int out_size)
{
    const float* fv          = (const float*)d_in[0];
    const float* te          = (const float*)d_in[1];
    const float* self_in_w   = (const float*)d_in[2];
    const float* self_in_b   = (const float*)d_in[3];
    const float* self_out_w  = (const float*)d_in[4];
    const float* self_out_b  = (const float*)d_in[5];
    const float* cross_in_w  = (const float*)d_in[6];
    const float* cross_in_b  = (const float*)d_in[7];
    const float* cross_out_w = (const float*)d_in[8];
    const float* cross_out_b = (const float*)d_in[9];
    const float* lin1_w      = (const float*)d_in[10];
    const float* lin1_b      = (const float*)d_in[11];
    const float* lin2_w      = (const float*)d_in[12];
    const float* lin2_b      = (const float*)d_in[13];
    const float* ln_w        = (const float*)d_in[14];
    const float* ln_b        = (const float*)d_in[15];
    const float* fc_out_w    = (const float*)d_in[16];

    float* out    = (float*)d_out;
    float* logits = out;
    float* ft     = out + (long)NDEC * VOC;

    float *px, *po, *pattn, *pq, *pqkv, *pkv, *pff, *pdec;
    cudaGetSymbolAddress((void**)&px,    g_x);
    cudaGetSymbolAddress((void**)&po,    g_o);
    cudaGetSymbolAddress((void**)&pattn, g_attn);
    cudaGetSymbolAddress((void**)&pq,    g_q);
    cudaGetSymbolAddress((void**)&pqkv,  g_qkv);
    cudaGetSymbolAddress((void**)&pkv,   g_kv);
    cudaGetSymbolAddress((void**)&pff,   g_ff);
    cudaGetSymbolAddress((void**)&pdec,  g_dec);

    pe_kernel<<<(NTOK * Dm + 255) / 256, 256>>>(te, px);

    dim3 agrid(Sq / TQ, NHh, Bq);

    for (int l = 0; l < NL; l++) {
        const float* siw = self_in_w  + (long)l * 3 * Dm * Dm;
        const float* sib = self_in_b  + (long)l * 3 * Dm;
        const float* sow = self_out_w + (long)l * Dm * Dm;
        const float* sob = self_out_b + (long)l * Dm;
        const float* ciw = cross_in_w  + (long)l * 3 * Dm * Dm;
        const float* cib = cross_in_b  + (long)l * 3 * Dm;
        const float* cow = cross_out_w + (long)l * Dm * Dm;
        const float* cob = cross_out_b + (long)l * Dm;
        const float* l1w = lin1_w + (long)l * FFd * Dm;
        const float* l1b = lin1_b + (long)l * FFd;
        const float* l2w = lin2_w + (long)l * Dm * FFd;
        const float* l2b = lin2_b + (long)l * Dm;
        const float* lw  = ln_w + (long)l * 3 * Dm;
        const float* lb  = ln_b + (long)l * 3 * Dm;

        // ---- self attention ----
        mma_gemm<<<gemm_grid(NTOK, 3 * Dm), 128>>>(px, siw, sib, pqkv,
                                                   NTOK, 3 * Dm, Dm, 0);
        attn_tile<<<agrid, 128>>>(pqkv, 3 * Dm,
                                  pqkv + Dm, 3 * Dm,
                                  pqkv + 2 * Dm, 3 * Dm,
                                  pattn, Dm, Sq, 1);
        mma_gemm<<<gemm_grid(NTOK, Dm), 128>>>(pattn, sow, sob, po,
                                               NTOK, Dm, Dm, 0);
        add_ln_kernel<<<NTOK, 256>>>(px, po, lw, lb);

        // ---- cross attention ----
        mma_gemm<<<gemm_grid(NTOK, Dm), 128>>>(px, ciw, cib, pq,
                                               NTOK, Dm, Dm, 0);
        mma_gemm<<<gemm_grid(NMEM, 2 * Dm), 128>>>(fv, ciw + (long)Dm * Dm,
                                                   cib + Dm, pkv,
                                                   NMEM, 2 * Dm, Dm, 0);
        attn_tile<<<agrid, 128>>>(pq, Dm,
                                  pkv, 2 * Dm,
                                  pkv + Dm, 2 * Dm,
                                  pattn, Dm, NV, 0);
        mma_gemm<<<gemm_grid(NTOK, Dm), 128>>>(pattn, cow, cob, po,
                                               NTOK, Dm, Dm, 0);
        add_ln_kernel<<<NTOK, 256>>>(px, po, lw + Dm, lb + Dm);

        // ---- FFN ----
        mma_gemm<<<gemm_grid(NTOK, FFd), 128>>>(px, l1w, l1b, pff,
                                                NTOK, FFd, Dm, 1);
        mma_gemm<<<gemm_grid(NTOK, Dm), 128>>>(pff, l2w, l2b, po,
                                               NTOK, Dm, FFd, 0);
        add_ln_kernel<<<NTOK, 256>>>(px, po, lw + 2 * Dm, lb + 2 * Dm);
    }

    dec_gather<<<(NDEC * Dm + 255) / 256, 256>>>(px, pdec);
    mma_gemm<<<gemm_grid(NDEC, VOC), 128>>>(pdec, fc_out_w, nullptr, logits,
                                            NDEC, VOC, Dm, 0);
    ft_softmax<<<NDEC, 256>>>(pdec, ft);
}

// round 9
// speedup vs baseline: 1.3058x; 1.2428x over previous
#include <cuda_runtime.h>
#include <cuda_fp16.h>
#include <math.h>
#include <stdint.h>

#define Bq   16
#define Sq   256
#define NV   196
#define Dm   768
#define FFd  2048
#define VOC  30522
#define NL   6
#define NHh  8
#define HD   96
#define NTOK (Bq*Sq)        // 4096
#define NMEM (Bq*NV)        // 3136
#define NDEC (Bq*(Sq-1))    // 4080

// -------- scratch (device globals; no allocations allowed) --------
__device__ float g_x   [NTOK*Dm];
__device__ float g_o   [NTOK*Dm];
__device__ float g_attn[NTOK*Dm];
__device__ float g_q   [NTOK*Dm];
__device__ float g_qkv [NTOK*3*Dm];
__device__ float g_kv  [NMEM*2*Dm];
__device__ float g_ff  [NTOK*FFd];
__device__ float g_dec [NDEC*Dm];

// ================== FP16 tensor-core GEMM (m16n8k16 HMMA) ==================
// C[M,N] = A[M,K] @ W[N,K]^T (+bias)(+relu), fp32 accumulate.
// 128x128 block tile, BK=16 halves, 8 warps of 64x32, double-buffered smem.
// smem rows are half2-packed, stride PADW=12 words -> conflict-free fragment
// reads (g*12 mod 32 tiles all banks for g=0..7, +t4 stays disjoint).
#define BM 128
#define BN 128
#define BK 16
#define PADW 12

__device__ __forceinline__ uint32_t packh2(float x, float y) {
    __half2 h = __floats2half2_rn(x, y);
    return *(uint32_t*)&h;
}

__device__ __forceinline__ void mma_f16(
    float& c0, float& c1, float& c2, float& c3,
    uint32_t a0, uint32_t a1, uint32_t a2, uint32_t a3,
    uint32_t b0, uint32_t b1)
{
    asm volatile(
        "mma.sync.aligned.m16n8k16.row.col.f32.f16.f16.f32 "
        "{%0,%1,%2,%3}, {%4,%5,%6,%7}, {%8,%9}, {%0,%1,%2,%3};"
        : "+f"(c0), "+f"(c1), "+f"(c2), "+f"(c3)
        : "r"(a0), "r"(a1), "r"(a2), "r"(a3), "r"(b0), "r"(b1));
}

__global__ __launch_bounds__(256, 2) void mma_gemm(
    const float* __restrict__ A, const float* __restrict__ W,
    const float* __restrict__ bias, float* __restrict__ C,
    int M, int N, int K, int relu)
{
    __shared__ uint32_t As[2][BM * PADW];
    __shared__ uint32_t Bs[2][BN * PADW];

    int tid  = threadIdx.x;
    int wid  = tid >> 5, lane = tid & 31;
    int g    = lane >> 2;          // 0..7
    int t4   = lane & 3;           // 0..3
    int wm   = (wid >> 2) * 64;    // 0 / 64
    int wn   = (wid & 3) * 32;     // 0..96
    int m0   = blockIdx.y * BM, n0 = blockIdx.x * BN;

    // global-load mapping: tile = 128 rows x 16 floats = 512 float4; 2/thread
    int r0 = tid >> 2, q0 = tid & 3;          // idx0 = tid
    int r1 = r0 + 64;                          // idx1 = tid + 256 (same q)
    bool av0 = (m0 + r0) < M, av1 = (m0 + r1) < M;
    bool bv0 = (n0 + r0) < N, bv1 = (n0 + r1) < N;
    const float* Ap0 = A + (long)(m0 + r0) * K + q0 * 4;
    const float* Ap1 = A + (long)(m0 + r1) * K + q0 * 4;
    const float* Wp0 = W + (long)(n0 + r0) * K + q0 * 4;
    const float* Wp1 = W + (long)(n0 + r1) * K + q0 * 4;
    int sa0 = r0 * PADW + q0 * 2;
    int sa1 = r1 * PADW + q0 * 2;

    float acc[4][4][4];
    #pragma unroll
    for (int i = 0; i < 4; i++)
        #pragma unroll
        for (int j = 0; j < 4; j++)
            #pragma unroll
            for (int k = 0; k < 4; k++) acc[i][j][k] = 0.f;

    const float4 z4 = make_float4(0.f, 0.f, 0.f, 0.f);
    float4 ra0, ra1, rb0, rb1;

    #define STORE_H2(dst, saddr, v)                                        \
        *(uint2*)&(dst)[saddr] = make_uint2(packh2((v).x, (v).y),          \
                                            packh2((v).z, (v).w));

    // prologue: tile 0
    ra0 = av0 ? *(const float4*)(Ap0) : z4;
    ra1 = av1 ? *(const float4*)(Ap1) : z4;
    rb0 = bv0 ? *(const float4*)(Wp0) : z4;
    rb1 = bv1 ? *(const float4*)(Wp1) : z4;
    STORE_H2(As[0], sa0, ra0);
    STORE_H2(As[0], sa1, ra1);
    STORE_H2(Bs[0], sa0, rb0);
    STORE_H2(Bs[0], sa1, rb1);
    __syncthreads();

    int nk = K / BK;
    int buf = 0;
    for (int t = 0; t < nk; t++) {
        if (t + 1 < nk) {
            int ko = (t + 1) * BK;
            ra0 = av0 ? *(const float4*)(Ap0 + ko) : z4;
            ra1 = av1 ? *(const float4*)(Ap1 + ko) : z4;
            rb0 = bv0 ? *(const float4*)(Wp0 + ko) : z4;
            rb1 = bv1 ? *(const float4*)(Wp1 + ko) : z4;
        }
        const uint32_t* as = As[buf];
        const uint32_t* bs = Bs[buf];

        uint32_t af[4][4], bf[4][2];
        #pragma unroll
        for (int mt = 0; mt < 4; mt++) {
            int row = wm + mt * 16 + g;
            af[mt][0] = as[row * PADW + t4];
            af[mt][1] = as[(row + 8) * PADW + t4];
            af[mt][2] = as[row * PADW + t4 + 4];
            af[mt][3] = as[(row + 8) * PADW + t4 + 4];
        }
        #pragma unroll
        for (int nt = 0; nt < 4; nt++) {
            int col = wn + nt * 8 + g;
            bf[nt][0] = bs[col * PADW + t4];
            bf[nt][1] = bs[col * PADW + t4 + 4];
        }
        #pragma unroll
        for (int mt = 0; mt < 4; mt++)
            #pragma unroll
            for (int nt = 0; nt < 4; nt++)
                mma_f16(acc[mt][nt][0], acc[mt][nt][1], acc[mt][nt][2], acc[mt][nt][3],
                        af[mt][0], af[mt][1], af[mt][2], af[mt][3],
                        bf[nt][0], bf[nt][1]);

        if (t + 1 < nk) {
            __syncthreads();
            uint32_t* nas = As[buf ^ 1]; uint32_t* nbs = Bs[buf ^ 1];
            STORE_H2(nas, sa0, ra0);
            STORE_H2(nas, sa1, ra1);
            STORE_H2(nbs, sa0, rb0);
            STORE_H2(nbs, sa1, rb1);
            __syncthreads();
            buf ^= 1;
        }
    }
    #undef STORE_H2

    // epilogue
    #pragma unroll
    for (int mt = 0; mt < 4; mt++) {
        int row = m0 + wm + mt * 16 + g;
        #pragma unroll
        for (int nt = 0; nt < 4; nt++) {
            int col = n0 + wn + nt * 8 + t4 * 2;
            float v0 = acc[mt][nt][0], v1 = acc[mt][nt][1];
            float v2 = acc[mt][nt][2], v3 = acc[mt][nt][3];
            if (bias) {
                float b0 = (col < N) ? bias[col] : 0.f;
                float b1 = (col + 1 < N) ? bias[col + 1] : 0.f;
                v0 += b0; v1 += b1; v2 += b0; v3 += b1;
            }
            if (relu) {
                v0 = fmaxf(v0, 0.f); v1 = fmaxf(v1, 0.f);
                v2 = fmaxf(v2, 0.f); v3 = fmaxf(v3, 0.f);
            }
            if (row < M) {
                if (col + 1 < N) *(float2*)&C[(long)row * N + col] = make_float2(v0, v1);
                else if (col < N) C[(long)row * N + col] = v0;
            }
            if (row + 8 < M) {
                if (col + 1 < N) *(float2*)&C[(long)(row + 8) * N + col] = make_float2(v2, v3);
                else if (col < N) C[(long)(row + 8) * N + col] = v2;
            }
        }
    }
}

// ================== tiled smem attention ==================
#define TQ 16
#define KCH 32

__global__ __launch_bounds__(128) void attn_tile(
    const float* __restrict__ Q, int qs,
    const float* __restrict__ Kt, int ks,
    const float* __restrict__ Vt, int vs,
    float* __restrict__ O, int os,
    int Lk, int causal)
{
    __shared__ float Qs[TQ][97];
    __shared__ float Ks[KCH][97];
    __shared__ float Vs[KCH][HD];
    __shared__ float Sc[TQ][Sq];
    __shared__ float invr[TQ];

    int tid  = threadIdx.x;
    int warp = tid >> 5, lane = tid & 31;
    int q0   = blockIdx.x * TQ;
    int h    = blockIdx.y, b = blockIdx.z;

    const float* Qb = Q  + ((long)b * Sq + q0) * qs + h * HD;
    const float* Kb = Kt + (long)b * Lk * ks + h * HD;
    const float* Vb = Vt + (long)b * Lk * vs + h * HD;

    for (int i = tid; i < TQ * HD; i += 128) {
        int r = i / HD, c = i % HD;
        Qs[r][c] = Qb[(long)r * qs + c];
    }

    const float scale = rsqrtf((float)HD);
    int nch = (Lk + KCH - 1) / KCH;

    for (int kc = 0; kc < nch; kc++) {
        int k0 = kc * KCH;
        __syncthreads();
        for (int i = tid; i < KCH * HD; i += 128) {
            int r = i / HD, c = i % HD;
            Ks[r][c] = (k0 + r < Lk) ? Kb[(long)(k0 + r) * ks + c] : 0.f;
        }
        __syncthreads();
        int j = k0 + lane;
        float s0 = 0.f, s1 = 0.f, s2 = 0.f, s3 = 0.f;
        #pragma unroll 8
        for (int t = 0; t < HD; t++) {
            float kv = Ks[lane][t];
            s0 += Qs[warp*4+0][t] * kv;
            s1 += Qs[warp*4+1][t] * kv;
            s2 += Qs[warp*4+2][t] * kv;
            s3 += Qs[warp*4+3][t] * kv;
        }
        #pragma unroll
        for (int qi = 0; qi < 4; qi++) {
            int q = warp * 4 + qi;
            float s = (qi == 0) ? s0 : (qi == 1) ? s1 : (qi == 2) ? s2 : s3;
            s *= scale;
            if (j >= Lk || (causal && j > q0 + q)) s = -1e30f;
            Sc[q][j] = s;
        }
    }
    __syncthreads();

    int nk32 = nch * KCH;
    #pragma unroll
    for (int qi = 0; qi < 4; qi++) {
        int q = warp * 4 + qi;
        float mx = -1e30f;
        for (int j = lane; j < nk32; j += 32) mx = fmaxf(mx, Sc[q][j]);
        #pragma unroll
        for (int o = 16; o; o >>= 1) mx = fmaxf(mx, __shfl_xor_sync(~0u, mx, o));
        float sum = 0.f;
        for (int j = lane; j < nk32; j += 32) {
            float e = __expf(Sc[q][j] - mx);
            Sc[q][j] = e;
            sum += e;
        }
        #pragma unroll
        for (int o = 16; o; o >>= 1) sum += __shfl_xor_sync(~0u, sum, o);
        if (lane == 0) invr[q] = 1.f / sum;
    }

    int qa = tid >> 3;
    int dbase = (tid & 7) * 12;
    float acc[12];
    #pragma unroll
    for (int i = 0; i < 12; i++) acc[i] = 0.f;

    for (int kc = 0; kc < nch; kc++) {
        int k0 = kc * KCH;
        __syncthreads();
        for (int i = tid; i < KCH * HD; i += 128) {
            int r = i / HD, c = i % HD;
            Vs[r][c] = (k0 + r < Lk) ? Vb[(long)(k0 + r) * vs + c] : 0.f;
        }
        __syncthreads();
        #pragma unroll
        for (int j = 0; j < KCH; j++) {
            float p = Sc[qa][k0 + j];
            float4 v0 = *(const float4*)&Vs[j][dbase];
            float4 v1 = *(const float4*)&Vs[j][dbase + 4];
            float4 v2 = *(const float4*)&Vs[j][dbase + 8];
            acc[0] += p * v0.x; acc[1]  += p * v0.y; acc[2]  += p * v0.z; acc[3]  += p * v0.w;
            acc[4] += p * v1.x; acc[5]  += p * v1.y; acc[6]  += p * v1.z; acc[7]  += p * v1.w;
            acc[8] += p * v2.x; acc[9]  += p * v2.y; acc[10] += p * v2.z; acc[11] += p * v2.w;
        }
    }
    float inv = invr[qa];
    float* op = O + ((long)b * Sq + q0 + qa) * os + h * HD + dbase;
    *(float4*)&op[0] = make_float4(acc[0]*inv, acc[1]*inv, acc[2]*inv, acc[3]*inv);
    *(float4*)&op[4] = make_float4(acc[4]*inv, acc[5]*inv, acc[6]*inv, acc[7]*inv);
    *(float4*)&op[8] = make_float4(acc[8]*inv, acc[9]*inv, acc[10]*inv, acc[11]*inv);
}

// -------- residual add + layernorm (in-place on X) --------
__global__ __launch_bounds__(256) void add_ln_kernel(
    float* __restrict__ X, const float* __restrict__ Y,
    const float* __restrict__ w, const float* __restrict__ b)
{
    long t = blockIdx.x;
    int tid = threadIdx.x;
    __shared__ float red[256];
    float vals[3];
    float s = 0.f;
    #pragma unroll
    for (int i = 0; i < 3; i++) {
        int d = tid + i * 256;
        float v = X[t * Dm + d] + Y[t * Dm + d];
        vals[i] = v;
        s += v;
    }
    red[tid] = s; __syncthreads();
    for (int st = 128; st > 0; st >>= 1) {
        if (tid < st) red[tid] += red[tid + st];
        __syncthreads();
    }
    float mean = red[0] * (1.f / Dm);
    __syncthreads();
    float s2 = 0.f;
    #pragma unroll
    for (int i = 0; i < 3; i++) { float dv = vals[i] - mean; s2 += dv * dv; }
    red[tid] = s2; __syncthreads();
    for (int st = 128; st > 0; st >>= 1) {
        if (tid < st) red[tid] += red[tid + st];
        __syncthreads();
    }
    float rstd = rsqrtf(red[0] * (1.f / Dm) + 1e-5f);
    #pragma unroll
    for (int i = 0; i < 3; i++) {
        int d = tid + i * 256;
        X[t * Dm + d] = (vals[i] - mean) * rstd * w[d] + b[d];
    }
}

// -------- x = target_embed + sinusoid PE --------
__global__ void pe_kernel(const float* __restrict__ te, float* __restrict__ x)
{
    int idx = blockIdx.x * 256 + threadIdx.x;
    if (idx >= NTOK * Dm) return;
    int d = idx % Dm;
    int tok = idx / Dm;
    int s = tok % Sq;
    int j = d >> 1;
    float div = expf(-(float)(2 * j) * (logf(10000.f) / (float)Dm));
    float ang = (float)s * div;
    float p = (d & 1) ? cosf(ang) : sinf(ang);
    x[idx] = te[idx] + p;
}

// -------- gather dec = x[:, :S-1, :] --------
__global__ void dec_gather(const float* __restrict__ x, float* __restrict__ dec)
{
    int idx = blockIdx.x * 256 + threadIdx.x;
    if (idx >= NDEC * Dm) return;
    int d = idx % Dm;
    int r = idx / Dm;
    int b = r / (Sq - 1);
    int s = r % (Sq - 1);
    dec[idx] = x[((long)(b * Sq + s)) * Dm + d];
}

// -------- F_t = softmax(dec, axis=-1) --------
__global__ __launch_bounds__(256) void ft_softmax(
    const float* __restrict__ dec, float* __restrict__ out)
{
    long r = blockIdx.x;
    int tid = threadIdx.x;
    __shared__ float red[256];
    float v[3];
    float mx = -1e30f;
    #pragma unroll
    for (int i = 0; i < 3; i++) {
        v[i] = dec[r * Dm + tid + i * 256];
        mx = fmaxf(mx, v[i]);
    }
    red[tid] = mx; __syncthreads();
    for (int st = 128; st > 0; st >>= 1) {
        if (tid < st) red[tid] = fmaxf(red[tid], red[tid + st]);
        __syncthreads();
    }
    float m = red[0]; __syncthreads();
    float s = 0.f;
    #pragma unroll
    for (int i = 0; i < 3; i++) { v[i] = __expf(v[i] - m); s += v[i]; }
    red[tid] = s; __syncthreads();
    for (int st = 128; st > 0; st >>= 1) {
        if (tid < st) red[tid] += red[tid + st];
        __syncthreads();
    }
    float inv = 1.f / red[0];
    #pragma unroll
    for (int i = 0; i < 3; i++)
        out[r * Dm + tid + i * 256] = v[i] * inv;
}

static inline dim3 gemm_grid(int M, int N) {
    return dim3((N + BN - 1) / BN, (M + BM - 1) / BM);
}

extern "C" void kernel_launch(void* const* d_in, const int* in_sizes, int n_in,
                              void* d_out, int out_size)
{
    const float* fv          = (const float*)d_in[0];
    const float* te          = (const float*)d_in[1];
    const float* self_in_w   = (const float*)d_in[2];
    const float* self_in_b   = (const float*)d_in[3];
    const float* self_out_w  = (const float*)d_in[4];
    const float* self_out_b  = (const float*)d_in[5];
    const float* cross_in_w  = (const float*)d_in[6];
    const float* cross_in_b  = (const float*)d_in[7];
    const float* cross_out_w = (const float*)d_in[8];
    const float* cross_out_b = (const float*)d_in[9];
    const float* lin1_w      = (const float*)d_in[10];
    const float* lin1_b      = (const float*)d_in[11];
    const float* lin2_w      = (const float*)d_in[12];
    const float* lin2_b      = (const float*)d_in[13];
    const float* ln_w        = (const float*)d_in[14];
    const float* ln_b        = (const float*)d_in[15];
    const float* fc_out_w    = (const float*)d_in[16];

    float* out    = (float*)d_out;
    float* logits = out;
    float* ft     = out + (long)NDEC * VOC;

    float *px, *po, *pattn, *pq, *pqkv, *pkv, *pff, *pdec;
    cudaGetSymbolAddress((void**)&px,    g_x);
    cudaGetSymbolAddress((void**)&po,    g_o);
    cudaGetSymbolAddress((void**)&pattn, g_attn);
    cudaGetSymbolAddress((void**)&pq,    g_q);
    cudaGetSymbolAddress((void**)&pqkv,  g_qkv);
    cudaGetSymbolAddress((void**)&pkv,   g_kv);
    cudaGetSymbolAddress((void**)&pff,   g_ff);
    cudaGetSymbolAddress((void**)&pdec,  g_dec);

    pe_kernel<<<(NTOK * Dm + 255) / 256, 256>>>(te, px);

    dim3 agrid(Sq / TQ, NHh, Bq);

    for (int l = 0; l < NL; l++) {
        const float* siw = self_in_w  + (long)l * 3 * Dm * Dm;
        const float* sib = self_in_b  + (long)l * 3 * Dm;
        const float* sow = self_out_w + (long)l * Dm * Dm;
        const float* sob = self_out_b + (long)l * Dm;
        const float* ciw = cross_in_w  + (long)l * 3 * Dm * Dm;
        const float* cib = cross_in_b  + (long)l * 3 * Dm;
        const float* cow = cross_out_w + (long)l * Dm * Dm;
        const float* cob = cross_out_b + (long)l * Dm;
        const float* l1w = lin1_w + (long)l * FFd * Dm;
        const float* l1b = lin1_b + (long)l * FFd;
        const float* l2w = lin2_w + (long)l * Dm * FFd;
        const float* l2b = lin2_b + (long)l * Dm;
        const float* lw  = ln_w + (long)l * 3 * Dm;
        const float* lb  = ln_b + (long)l * 3 * Dm;

        // ---- self attention ----
        mma_gemm<<<gemm_grid(NTOK, 3 * Dm), 256>>>(px, siw, sib, pqkv,
                                                   NTOK, 3 * Dm, Dm, 0);
        attn_tile<<<agrid, 128>>>(pqkv, 3 * Dm,
                                  pqkv + Dm, 3 * Dm,
                                  pqkv + 2 * Dm, 3 * Dm,
                                  pattn, Dm, Sq, 1);
        mma_gemm<<<gemm_grid(NTOK, Dm), 256>>>(pattn, sow, sob, po,
                                               NTOK, Dm, Dm, 0);
        add_ln_kernel<<<NTOK, 256>>>(px, po, lw, lb);

        // ---- cross attention ----
        mma_gemm<<<gemm_grid(NTOK, Dm), 256>>>(px, ciw, cib, pq,
                                               NTOK, Dm, Dm, 0);
        mma_gemm<<<gemm_grid(NMEM, 2 * Dm), 256>>>(fv, ciw + (long)Dm * Dm,
                                                   cib + Dm, pkv,
                                                   NMEM, 2 * Dm, Dm, 0);
        attn_tile<<<agrid, 128>>>(pq, Dm,
                                  pkv, 2 * Dm,
                                  pkv + Dm, 2 * Dm,
                                  pattn, Dm, NV, 0);
        mma_gemm<<<gemm_grid(NTOK, Dm), 256>>>(pattn, cow, cob, po,
                                               NTOK, Dm, Dm, 0);
        add_ln_kernel<<<NTOK, 256>>>(px, po, lw + Dm, lb + Dm);

        // ---- FFN ----
        mma_gemm<<<gemm_grid(NTOK, FFd), 256>>>(px, l1w, l1b, pff,
                                                NTOK, FFd, Dm, 1);
        mma_gemm<<<gemm_grid(NTOK, Dm), 256>>>(pff, l2w, l2b, po,
                                               NTOK, Dm, FFd, 0);
        add_ln_kernel<<<NTOK, 256>>>(px, po, lw + 2 * Dm, lb + 2 * Dm);
    }

    dec_gather<<<(NDEC * Dm + 255) / 256, 256>>>(px, pdec);
    mma_gemm<<<gemm_grid(NDEC, VOC), 256>>>(pdec, fc_out_w, nullptr, logits,
                                            NDEC, VOC, Dm, 0);
    ft_softmax<<<NDEC, 256>>>(pdec, ft);
}

// round 10
// speedup vs baseline: 1.3969x; 1.0698x over previous
#include <cuda_runtime.h>
#include <cuda_fp16.h>
#include <math.h>
#include <stdint.h>

#define Bq   16
#define Sq   256
#define NV   196
#define Dm   768
#define FFd  2048
#define VOC  30522
#define NL   6
#define NHh  8
#define HD   96
#define NTOK (Bq*Sq)        // 4096
#define NMEM (Bq*NV)        // 3136
#define NDEC (Bq*(Sq-1))    // 4080

// -------- scratch (device globals; no allocations allowed) --------
__device__ float g_x   [NTOK*Dm];
__device__ float g_o   [NTOK*Dm];
__device__ float g_attn[NTOK*Dm];
__device__ float g_q   [NTOK*Dm];
__device__ float g_qkv [NTOK*3*Dm];
__device__ float g_kv  [NMEM*2*Dm];
__device__ float g_ff  [NTOK*FFd];
__device__ float g_dec [NDEC*Dm];

// ================== FP16 tensor-core GEMM (m16n8k16 HMMA + ldmatrix) =====
// C[M,N] = A[M,K] @ W[N,K]^T (+bias)(+relu), fp32 accumulate.
// 128x128 block tile, BK=16 halves, 8 warps of 64x32, double-buffered smem.
// smem rows half2-packed, stride PADW=12 words; ldmatrix row stride 48B ->
// 8 rows tile all 32 banks exactly once (conflict-free).
#define BM 128
#define BN 128
#define BK 16
#define PADW 12

__device__ __forceinline__ uint32_t packh2(float x, float y) {
    __half2 h = __floats2half2_rn(x, y);
    return *(uint32_t*)&h;
}

__device__ __forceinline__ uint32_t cvta_smem(const void* p) {
    uint32_t a;
    asm("{ .reg .u64 t; cvta.to.shared.u64 t, %1; cvt.u32.u64 %0, t; }"
        : "=r"(a) : "l"(p));
    return a;
}

__device__ __forceinline__ void mma_f16(
    float& c0, float& c1, float& c2, float& c3,
    uint32_t a0, uint32_t a1, uint32_t a2, uint32_t a3,
    uint32_t b0, uint32_t b1)
{
    asm volatile(
        "mma.sync.aligned.m16n8k16.row.col.f32.f16.f16.f32 "
        "{%0,%1,%2,%3}, {%4,%5,%6,%7}, {%8,%9}, {%0,%1,%2,%3};"
        : "+f"(c0), "+f"(c1), "+f"(c2), "+f"(c3)
        : "r"(a0), "r"(a1), "r"(a2), "r"(a3), "r"(b0), "r"(b1));
}

#define LDM_X4(r, addr) \
    asm volatile("ldmatrix.sync.aligned.m8n8.x4.shared.b16 {%0,%1,%2,%3}, [%4];" \
        : "=r"((r)[0]), "=r"((r)[1]), "=r"((r)[2]), "=r"((r)[3]) : "r"(addr))

__global__ __launch_bounds__(256, 2) void mma_gemm(
    const float* __restrict__ A, const float* __restrict__ W,
    const float* __restrict__ bias, float* __restrict__ C,
    int M, int N, int K, int relu)
{
    __shared__ uint32_t As[2][BM * PADW];
    __shared__ uint32_t Bs[2][BN * PADW];

    int tid  = threadIdx.x;
    int wid  = tid >> 5, lane = tid & 31;
    int g    = lane >> 2;          // 0..7
    int t4   = lane & 3;           // 0..3
    int wm   = (wid >> 2) * 64;    // 0 / 64
    int wn   = (wid & 3) * 32;     // 0..96
    int m0   = blockIdx.y * BM, n0 = blockIdx.x * BN;

    // global-load mapping: tile = 128 rows x 16 floats = 512 float4; 2/thread
    int r0 = tid >> 2, q0 = tid & 3;          // idx0 = tid
    int r1 = r0 + 64;                          // idx1 = tid + 256 (same q)
    bool av0 = (m0 + r0) < M, av1 = (m0 + r1) < M;
    bool bv0 = (n0 + r0) < N, bv1 = (n0 + r1) < N;
    const float* Ap0 = A + (long)(m0 + r0) * K + q0 * 4;
    const float* Ap1 = A + (long)(m0 + r1) * K + q0 * 4;
    const float* Wp0 = W + (long)(n0 + r0) * K + q0 * 4;
    const float* Wp1 = W + (long)(n0 + r1) * K + q0 * 4;
    int sa0 = r0 * PADW + q0 * 2;
    int sa1 = r1 * PADW + q0 * 2;

    // ldmatrix per-lane source addresses (byte offsets within a buffer)
    //   A (mt tile): lanes 0-15 -> rows wm+(lane&15), k-half (lane>>4)
    int rA  = lane & 15, khA = lane >> 4;
    uint32_t aoff = (uint32_t)(((wm + rA) * PADW + khA * 4) * 4);
    //   B (nt pair p): quad = lane>>3; rows wn+p*16+(quad>>1)*8+(lane&7),
    //   k-half (quad&1)
    int qd = lane >> 3, rB = lane & 7;
    uint32_t boff = (uint32_t)(((wn + ((qd >> 1) * 8) + rB) * PADW + (qd & 1) * 4) * 4);

    uint32_t asb[2] = { cvta_smem(As[0]), cvta_smem(As[1]) };
    uint32_t bsb[2] = { cvta_smem(Bs[0]), cvta_smem(Bs[1]) };

    float acc[4][4][4];
    #pragma unroll
    for (int i = 0; i < 4; i++)
        #pragma unroll
        for (int j = 0; j < 4; j++)
            #pragma unroll
            for (int k = 0; k < 4; k++) acc[i][j][k] = 0.f;

    const float4 z4 = make_float4(0.f, 0.f, 0.f, 0.f);
    float4 ra0, ra1, rb0, rb1;

    #define STORE_H2(dst, saddr, v)                                        \
        *(uint2*)&(dst)[saddr] = make_uint2(packh2((v).x, (v).y),          \
                                            packh2((v).z, (v).w));

    // prologue: tile 0
    ra0 = av0 ? *(const float4*)(Ap0) : z4;
    ra1 = av1 ? *(const float4*)(Ap1) : z4;
    rb0 = bv0 ? *(const float4*)(Wp0) : z4;
    rb1 = bv1 ? *(const float4*)(Wp1) : z4;
    STORE_H2(As[0], sa0, ra0);
    STORE_H2(As[0], sa1, ra1);
    STORE_H2(Bs[0], sa0, rb0);
    STORE_H2(Bs[0], sa1, rb1);
    __syncthreads();

    int nk = K / BK;
    int buf = 0;
    for (int t = 0; t < nk; t++) {
        if (t + 1 < nk) {
            int ko = (t + 1) * BK;
            ra0 = av0 ? *(const float4*)(Ap0 + ko) : z4;
            ra1 = av1 ? *(const float4*)(Ap1 + ko) : z4;
            rb0 = bv0 ? *(const float4*)(Wp0 + ko) : z4;
            rb1 = bv1 ? *(const float4*)(Wp1 + ko) : z4;
        }

        uint32_t af[4][4], bf[4][2];
        #pragma unroll
        for (int mt = 0; mt < 4; mt++)
            LDM_X4(af[mt], asb[buf] + aoff + (uint32_t)(mt * 16 * PADW * 4));
        #pragma unroll
        for (int p = 0; p < 2; p++) {
            uint32_t bb[4];
            LDM_X4(bb, bsb[buf] + boff + (uint32_t)(p * 16 * PADW * 4));
            bf[2*p][0]   = bb[0]; bf[2*p][1]   = bb[1];
            bf[2*p+1][0] = bb[2]; bf[2*p+1][1] = bb[3];
        }
        #pragma unroll
        for (int mt = 0; mt < 4; mt++)
            #pragma unroll
            for (int nt = 0; nt < 4; nt++)
                mma_f16(acc[mt][nt][0], acc[mt][nt][1], acc[mt][nt][2], acc[mt][nt][3],
                        af[mt][0], af[mt][1], af[mt][2], af[mt][3],
                        bf[nt][0], bf[nt][1]);

        if (t + 1 < nk) {
            __syncthreads();
            uint32_t* nas = As[buf ^ 1]; uint32_t* nbs = Bs[buf ^ 1];
            STORE_H2(nas, sa0, ra0);
            STORE_H2(nas, sa1, ra1);
            STORE_H2(nbs, sa0, rb0);
            STORE_H2(nbs, sa1, rb1);
            __syncthreads();
            buf ^= 1;
        }
    }
    #undef STORE_H2

    // epilogue
    #pragma unroll
    for (int mt = 0; mt < 4; mt++) {
        int row = m0 + wm + mt * 16 + g;
        #pragma unroll
        for (int nt = 0; nt < 4; nt++) {
            int col = n0 + wn + nt * 8 + t4 * 2;
            float v0 = acc[mt][nt][0], v1 = acc[mt][nt][1];
            float v2 = acc[mt][nt][2], v3 = acc[mt][nt][3];
            if (bias) {
                float b0 = (col < N) ? bias[col] : 0.f;
                float b1 = (col + 1 < N) ? bias[col + 1] : 0.f;
                v0 += b0; v1 += b1; v2 += b0; v3 += b1;
            }
            if (relu) {
                v0 = fmaxf(v0, 0.f); v1 = fmaxf(v1, 0.f);
                v2 = fmaxf(v2, 0.f); v3 = fmaxf(v3, 0.f);
            }
            if (row < M) {
                if (col + 1 < N) *(float2*)&C[(long)row * N + col] = make_float2(v0, v1);
                else if (col < N) C[(long)row * N + col] = v0;
            }
            if (row + 8 < M) {
                if (col + 1 < N) *(float2*)&C[(long)(row + 8) * N + col] = make_float2(v2, v3);
                else if (col < N) C[(long)(row + 8) * N + col] = v2;
            }
        }
    }
}

// ================== tiled smem attention ==================
#define TQ 16
#define KCH 32

__global__ __launch_bounds__(128) void attn_tile(
    const float* __restrict__ Q, int qs,
    const float* __restrict__ Kt, int ks,
    const float* __restrict__ Vt, int vs,
    float* __restrict__ O, int os,
    int Lk, int causal)
{
    __shared__ float Qs[TQ][97];
    __shared__ float Ks[KCH][97];
    __shared__ float Vs[KCH][HD];
    __shared__ float Sc[TQ][Sq];
    __shared__ float invr[TQ];

    int tid  = threadIdx.x;
    int warp = tid >> 5, lane = tid & 31;
    int q0   = blockIdx.x * TQ;
    int h    = blockIdx.y, b = blockIdx.z;

    const float* Qb = Q  + ((long)b * Sq + q0) * qs + h * HD;
    const float* Kb = Kt + (long)b * Lk * ks + h * HD;
    const float* Vb = Vt + (long)b * Lk * vs + h * HD;

    for (int i = tid; i < TQ * HD; i += 128) {
        int r = i / HD, c = i % HD;
        Qs[r][c] = Qb[(long)r * qs + c];
    }

    const float scale = rsqrtf((float)HD);
    int nch = (Lk + KCH - 1) / KCH;

    for (int kc = 0; kc < nch; kc++) {
        int k0 = kc * KCH;
        __syncthreads();
        for (int i = tid; i < KCH * HD; i += 128) {
            int r = i / HD, c = i % HD;
            Ks[r][c] = (k0 + r < Lk) ? Kb[(long)(k0 + r) * ks + c] : 0.f;
        }
        __syncthreads();
        int j = k0 + lane;
        float s0 = 0.f, s1 = 0.f, s2 = 0.f, s3 = 0.f;
        #pragma unroll 8
        for (int t = 0; t < HD; t++) {
            float kv = Ks[lane][t];
            s0 += Qs[warp*4+0][t] * kv;
            s1 += Qs[warp*4+1][t] * kv;
            s2 += Qs[warp*4+2][t] * kv;
            s3 += Qs[warp*4+3][t] * kv;
        }
        #pragma unroll
        for (int qi = 0; qi < 4; qi++) {
            int q = warp * 4 + qi;
            float s = (qi == 0) ? s0 : (qi == 1) ? s1 : (qi == 2) ? s2 : s3;
            s *= scale;
            if (j >= Lk || (causal && j > q0 + q)) s = -1e30f;
            Sc[q][j] = s;
        }
    }
    __syncthreads();

    int nk32 = nch * KCH;
    #pragma unroll
    for (int qi = 0; qi < 4; qi++) {
        int q = warp * 4 + qi;
        float mx = -1e30f;
        for (int j = lane; j < nk32; j += 32) mx = fmaxf(mx, Sc[q][j]);
        #pragma unroll
        for (int o = 16; o; o >>= 1) mx = fmaxf(mx, __shfl_xor_sync(~0u, mx, o));
        float sum = 0.f;
        for (int j = lane; j < nk32; j += 32) {
            float e = __expf(Sc[q][j] - mx);
            Sc[q][j] = e;
            sum += e;
        }
        #pragma unroll
        for (int o = 16; o; o >>= 1) sum += __shfl_xor_sync(~0u, sum, o);
        if (lane == 0) invr[q] = 1.f / sum;
    }

    int qa = tid >> 3;
    int dbase = (tid & 7) * 12;
    float acc[12];
    #pragma unroll
    for (int i = 0; i < 12; i++) acc[i] = 0.f;

    for (int kc = 0; kc < nch; kc++) {
        int k0 = kc * KCH;
        __syncthreads();
        for (int i = tid; i < KCH * HD; i += 128) {
            int r = i / HD, c = i % HD;
            Vs[r][c] = (k0 + r < Lk) ? Vb[(long)(k0 + r) * vs + c] : 0.f;
        }
        __syncthreads();
        #pragma unroll
        for (int j = 0; j < KCH; j++) {
            float p = Sc[qa][k0 + j];
            float4 v0 = *(const float4*)&Vs[j][dbase];
            float4 v1 = *(const float4*)&Vs[j][dbase + 4];
            float4 v2 = *(const float4*)&Vs[j][dbase + 8];
            acc[0] += p * v0.x; acc[1]  += p * v0.y; acc[2]  += p * v0.z; acc[3]  += p * v0.w;
            acc[4] += p * v1.x; acc[5]  += p * v1.y; acc[6]  += p * v1.z; acc[7]  += p * v1.w;
            acc[8] += p * v2.x; acc[9]  += p * v2.y; acc[10] += p * v2.z; acc[11] += p * v2.w;
        }
    }
    float inv = invr[qa];
    float* op = O + ((long)b * Sq + q0 + qa) * os + h * HD + dbase;
    *(float4*)&op[0] = make_float4(acc[0]*inv, acc[1]*inv, acc[2]*inv, acc[3]*inv);
    *(float4*)&op[4] = make_float4(acc[4]*inv, acc[5]*inv, acc[6]*inv, acc[7]*inv);
    *(float4*)&op[8] = make_float4(acc[8]*inv, acc[9]*inv, acc[10]*inv, acc[11]*inv);
}

// -------- residual add + layernorm (in-place on X) --------
__global__ __launch_bounds__(256) void add_ln_kernel(
    float* __restrict__ X, const float* __restrict__ Y,
    const float* __restrict__ w, const float* __restrict__ b)
{
    long t = blockIdx.x;
    int tid = threadIdx.x;
    __shared__ float red[256];
    float vals[3];
    float s = 0.f;
    #pragma unroll
    for (int i = 0; i < 3; i++) {
        int d = tid + i * 256;
        float v = X[t * Dm + d] + Y[t * Dm + d];
        vals[i] = v;
        s += v;
    }
    red[tid] = s; __syncthreads();
    for (int st = 128; st > 0; st >>= 1) {
        if (tid < st) red[tid] += red[tid + st];
        __syncthreads();
    }
    float mean = red[0] * (1.f / Dm);
    __syncthreads();
    float s2 = 0.f;
    #pragma unroll
    for (int i = 0; i < 3; i++) { float dv = vals[i] - mean; s2 += dv * dv; }
    red[tid] = s2; __syncthreads();
    for (int st = 128; st > 0; st >>= 1) {
        if (tid < st) red[tid] += red[tid + st];
        __syncthreads();
    }
    float rstd = rsqrtf(red[0] * (1.f / Dm) + 1e-5f);
    #pragma unroll
    for (int i = 0; i < 3; i++) {
        int d = tid + i * 256;
        X[t * Dm + d] = (vals[i] - mean) * rstd * w[d] + b[d];
    }
}

// -------- x = target_embed + sinusoid PE --------
__global__ void pe_kernel(const float* __restrict__ te, float* __restrict__ x)
{
    int idx = blockIdx.x * 256 + threadIdx.x;
    if (idx >= NTOK * Dm) return;
    int d = idx % Dm;
    int tok = idx / Dm;
    int s = tok % Sq;
    int j = d >> 1;
    float div = expf(-(float)(2 * j) * (logf(10000.f) / (float)Dm));
    float ang = (float)s * div;
    float p = (d & 1) ? cosf(ang) : sinf(ang);
    x[idx] = te[idx] + p;
}

// -------- gather dec = x[:, :S-1, :] --------
__global__ void dec_gather(const float* __restrict__ x, float* __restrict__ dec)
{
    int idx = blockIdx.x * 256 + threadIdx.x;
    if (idx >= NDEC * Dm) return;
    int d = idx % Dm;
    int r = idx / Dm;
    int b = r / (Sq - 1);
    int s = r % (Sq - 1);
    dec[idx] = x[((long)(b * Sq + s)) * Dm + d];
}

// -------- F_t = softmax(dec, axis=-1) --------
__global__ __launch_bounds__(256) void ft_softmax(
    const float* __restrict__ dec, float* __restrict__ out)
{
    long r = blockIdx.x;
    int tid = threadIdx.x;
    __shared__ float red[256];
    float v[3];
    float mx = -1e30f;
    #pragma unroll
    for (int i = 0; i < 3; i++) {
        v[i] = dec[r * Dm + tid + i * 256];
        mx = fmaxf(mx, v[i]);
    }
    red[tid] = mx; __syncthreads();
    for (int st = 128; st > 0; st >>= 1) {
        if (tid < st) red[tid] = fmaxf(red[tid], red[tid + st]);
        __syncthreads();
    }
    float m = red[0]; __syncthreads();
    float s = 0.f;
    #pragma unroll
    for (int i = 0; i < 3; i++) { v[i] = __expf(v[i] - m); s += v[i]; }
    red[tid] = s; __syncthreads();
    for (int st = 128; st > 0; st >>= 1) {
        if (tid < st) red[tid] += red[tid + st];
        __syncthreads();
    }
    float inv = 1.f / red[0];
    #pragma unroll
    for (int i = 0; i < 3; i++)
        out[r * Dm + tid + i * 256] = v[i] * inv;
}

static inline dim3 gemm_grid(int M, int N) {
    return dim3((N + BN - 1) / BN, (M + BM - 1) / BM);
}

extern "C" void kernel_launch(void* const* d_in, const int* in_sizes, int n_in,
                              void* d_out, int out_size)
{
    const float* fv          = (const float*)d_in[0];
    const float* te          = (const float*)d_in[1];
    const float* self_in_w   = (const float*)d_in[2];
    const float* self_in_b   = (const float*)d_in[3];
    const float* self_out_w  = (const float*)d_in[4];
    const float* self_out_b  = (const float*)d_in[5];
    const float* cross_in_w  = (const float*)d_in[6];
    const float* cross_in_b  = (const float*)d_in[7];
    const float* cross_out_w = (const float*)d_in[8];
    const float* cross_out_b = (const float*)d_in[9];
    const float* lin1_w      = (const float*)d_in[10];
    const float* lin1_b      = (const float*)d_in[11];
    const float* lin2_w      = (const float*)d_in[12];
    const float* lin2_b      = (const float*)d_in[13];
    const float* ln_w        = (const float*)d_in[14];
    const float* ln_b        = (const float*)d_in[15];
    const float* fc_out_w    = (const float*)d_in[16];

    float* out    = (float*)d_out;
    float* logits = out;
    float* ft     = out + (long)NDEC * VOC;

    float *px, *po, *pattn, *pq, *pqkv, *pkv, *pff, *pdec;
    cudaGetSymbolAddress((void**)&px,    g_x);
    cudaGetSymbolAddress((void**)&po,    g_o);
    cudaGetSymbolAddress((void**)&pattn, g_attn);
    cudaGetSymbolAddress((void**)&pq,    g_q);
    cudaGetSymbolAddress((void**)&pqkv,  g_qkv);
    cudaGetSymbolAddress((void**)&pkv,   g_kv);
    cudaGetSymbolAddress((void**)&pff,   g_ff);
    cudaGetSymbolAddress((void**)&pdec,  g_dec);

    pe_kernel<<<(NTOK * Dm + 255) / 256, 256>>>(te, px);

    dim3 agrid(Sq / TQ, NHh, Bq);

    for (int l = 0; l < NL; l++) {
        const float* siw = self_in_w  + (long)l * 3 * Dm * Dm;
        const float* sib = self_in_b  + (long)l * 3 * Dm;
        const float* sow = self_out_w + (long)l * Dm * Dm;
        const float* sob = self_out_b + (long)l * Dm;
        const float* ciw = cross_in_w  + (long)l * 3 * Dm * Dm;
        const float* cib = cross_in_b  + (long)l * 3 * Dm;
        const float* cow = cross_out_w + (long)l * Dm * Dm;
        const float* cob = cross_out_b + (long)l * Dm;
        const float* l1w = lin1_w + (long)l * FFd * Dm;
        const float* l1b = lin1_b + (long)l * FFd;
        const float* l2w = lin2_w + (long)l * Dm * FFd;
        const float* l2b = lin2_b + (long)l * Dm;
        const float* lw  = ln_w + (long)l * 3 * Dm;
        const float* lb  = ln_b + (long)l * 3 * Dm;

        // ---- self attention ----
        mma_gemm<<<gemm_grid(NTOK, 3 * Dm), 256>>>(px, siw, sib, pqkv,
                                                   NTOK, 3 * Dm, Dm, 0);
        attn_tile<<<agrid, 128>>>(pqkv, 3 * Dm,
                                  pqkv + Dm, 3 * Dm,
                                  pqkv + 2 * Dm, 3 * Dm,
                                  pattn, Dm, Sq, 1);
        mma_gemm<<<gemm_grid(NTOK, Dm), 256>>>(pattn, sow, sob, po,
                                               NTOK, Dm, Dm, 0);
        add_ln_kernel<<<NTOK, 256>>>(px, po, lw, lb);

        // ---- cross attention ----
        mma_gemm<<<gemm_grid(NTOK, Dm), 256>>>(px, ciw, cib, pq,
                                               NTOK, Dm, Dm, 0);
        mma_gemm<<<gemm_grid(NMEM, 2 * Dm), 256>>>(fv, ciw + (long)Dm * Dm,
                                                   cib + Dm, pkv,
                                                   NMEM, 2 * Dm, Dm, 0);
        attn_tile<<<agrid, 128>>>(pq, Dm,
                                  pkv, 2 * Dm,
                                  pkv + Dm, 2 * Dm,
                                  pattn, Dm, NV, 0);
        mma_gemm<<<gemm_grid(NTOK, Dm), 256>>>(pattn, cow, cob, po,
                                               NTOK, Dm, Dm, 0);
        add_ln_kernel<<<NTOK, 256>>>(px, po, lw + Dm, lb + Dm);

        // ---- FFN ----
        mma_gemm<<<gemm_grid(NTOK, FFd), 256>>>(px, l1w, l1b, pff,
                                                NTOK, FFd, Dm, 1);
        mma_gemm<<<gemm_grid(NTOK, Dm), 256>>>(pff, l2w, l2b, po,
                                               NTOK, Dm, FFd, 0);
        add_ln_kernel<<<NTOK, 256>>>(px, po, lw + 2 * Dm, lb + 2 * Dm);
    }

    dec_gather<<<(NDEC * Dm + 255) / 256, 256>>>(px, pdec);
    mma_gemm<<<gemm_grid(NDEC, VOC), 256>>>(pdec, fc_out_w, nullptr, logits,
                                            NDEC, VOC, Dm, 0);
    ft_softmax<<<NDEC, 256>>>(pdec, ft);
}